// round 14
// baseline (speedup 1.0000x reference)
#include <cuda_runtime.h>
#include <cuda_fp16.h>
#include <cstdint>
#include <math.h>

#define NL 3
#define WIDTH 4
#define H 512
#define B 32
#define S 512
#define SP (S + 2*WIDTH)      // 520
#define CIN ((WIDTH+1)*H)     // 2560
#define BSR (B*S)             // 16384

// tiles: BM=128, BN=256, BK=32, 512 threads (16 warps, 2x8), warp tile 64x32
#define BM 128
#define BN 256
#define BK 32
#define NSTG 6
#define AROWB 80                      // smem row stride bytes (32 halfs + 16B pad)
#define ASTGB (BM * AROWB)            // 10240
#define BSTGB (BN * AROWB)            // 20480
#define DSMEM_BYTES (NSTG*(ASTGB + BSTGB))   // 184320

// ---------------- scratch (fp16 activations/weights) ----------------
__device__ __align__(256) __half g_pad[2][(size_t)B*SP*H];
__device__ __align__(256) __half g_x [2][(size_t)BSR*H];
__device__ __align__(256) __half g_x2[2][(size_t)BSR*H];
__device__ __align__(256) __half g_cwT[6][(size_t)H*CIN];      // conv W^T [n][k]
__device__ __align__(256) __half g_hwT[12][(size_t)(2*H)*H];   // hw W^T interleaved [n'][k]

// ---------------- helpers ----------------
__device__ __forceinline__ uint32_t smem_u32(const void* p) {
    uint32_t a;
    asm("{ .reg .u64 t; cvta.to.shared.u64 t, %1; cvt.u32.u64 %0, t; }" : "=r"(a) : "l"(p));
    return a;
}
__device__ __forceinline__ void cp16(uint32_t s, const void* g) {
    asm volatile("cp.async.ca.shared.global [%0], [%1], 16;" :: "r"(s), "l"(g));
}
#define CP_COMMIT() asm volatile("cp.async.commit_group;" ::: "memory")
#define CP_WAIT4()  asm volatile("cp.async.wait_group 4;" ::: "memory")

#define LDSM_X4(r0,r1,r2,r3,addr) \
    asm volatile("ldmatrix.sync.aligned.m8n8.x4.shared.b16 {%0,%1,%2,%3}, [%4];" \
        : "=r"(r0),"=r"(r1),"=r"(r2),"=r"(r3) : "r"(addr))

__device__ __forceinline__ void mma_f16(float* d, const uint32_t* a, uint32_t b0, uint32_t b1) {
    asm volatile("mma.sync.aligned.m16n8k16.row.col.f32.f16.f16.f32 "
        "{%0,%1,%2,%3},{%4,%5,%6,%7},{%8,%9},{%0,%1,%2,%3};"
        : "+f"(d[0]), "+f"(d[1]), "+f"(d[2]), "+f"(d[3])
        : "r"(a[0]), "r"(a[1]), "r"(a[2]), "r"(a[3]), "r"(b0), "r"(b1));
}

__device__ __forceinline__ uint4 cvt8(float4 a, float4 b) {
    __half2 h0 = __floats2half2_rn(a.x, a.y), h1 = __floats2half2_rn(a.z, a.w);
    __half2 h2 = __floats2half2_rn(b.x, b.y), h3 = __floats2half2_rn(b.z, b.w);
    uint4 r;
    r.x = *(uint32_t*)&h0; r.y = *(uint32_t*)&h1;
    r.z = *(uint32_t*)&h2; r.w = *(uint32_t*)&h3;
    return r;
}

// ---------------- prep: conv weight transpose [CIN][H] -> fp16 [H][CIN] ----------------
__global__ void prep_conv(const float* __restrict__ fwd_W, const float* __restrict__ bwd_W) {
    __shared__ float t[32][33];
    int z = blockIdx.z;               // dir*3 + layer
    int dir = z / 3, layer = z % 3;
    const float* src = (dir ? bwd_W : fwd_W) + (size_t)layer * CIN * H;
    __half* dst = g_cwT[z];
    int k0 = blockIdx.x * 32, n0 = blockIdx.y * 32;
    int tx = threadIdx.x, ty = threadIdx.y;
#pragma unroll
    for (int j = 0; j < 4; j++)
        t[ty + 8*j][tx] = src[(size_t)(k0 + ty + 8*j) * H + n0 + tx];
    __syncthreads();
#pragma unroll
    for (int j = 0; j < 4; j++)
        dst[(size_t)(n0 + ty + 8*j) * CIN + k0 + tx] = __float2half_rn(t[tx][ty + 8*j]);
}

// ---------------- prep: hw weight transpose + interleave -> fp16 [1024][512] ----------------
// dst row n' <- src col (n'&1)*512 + (n'>>1)   (even = nonlin, odd = gate)
__global__ void prep_hw(const float* __restrict__ fwd_hw_W, const float* __restrict__ bwd_hw_W) {
    __shared__ float t[32][33];
    int z = blockIdx.z;               // (dir*3+layer)*2 + step
    int dir = z / 6, rem = z % 6, layer = rem / 2, step = rem % 2;
    const float* src = (dir ? bwd_hw_W : fwd_hw_W) + ((size_t)layer * 2 + step) * (size_t)H * (2*H);
    __half* dst = g_hwT[z];
    int k0 = blockIdx.x * 32, np0 = blockIdx.y * 32;
    int j0 = np0 >> 1;
    int tx = threadIdx.x, ty = threadIdx.y;
    int half_ = tx >> 4, jj = tx & 15;
    int i = jj * 2 + half_;
#pragma unroll
    for (int j = 0; j < 4; j++)
        t[ty + 8*j][i] = src[(size_t)(k0 + ty + 8*j) * (2*H) + half_ * H + j0 + jj];
    __syncthreads();
#pragma unroll
    for (int j = 0; j < 4; j++)
        dst[(size_t)(np0 + ty + 8*j) * H + k0 + tx] = __float2half_rn(t[tx][ty + 8*j]);
}

// ---------------- pad kernel: build fp16 [B, S+8, H] padded sequence ----------------
__global__ void pad_kernel(const float* __restrict__ inputs,
                           const float* __restrict__ fwd_pads,
                           const float* __restrict__ bwd_pads,
                           int layer, int use_inputs)
{
    int dir = blockIdx.y;
    long idx = (long)blockIdx.x * blockDim.x + threadIdx.x;   // 8-half granularity
    const long n8 = (long)B * SP * H / 8;
    if (idx >= n8) return;
    long e = idx * 8;
    int h = (int)(e % H);
    long bp = e / H;
    int p = (int)(bp % SP);
    int b = (int)(bp / SP);

    uint4 o;
    if (p < WIDTH) {
        const float* s = &fwd_pads[((long)layer*WIDTH + p)*H + h];
        o = cvt8(*(const float4*)s, *(const float4*)(s + 4));
    } else if (p >= S + WIDTH) {
        const float* s = &bwd_pads[((long)layer*WIDTH + (p - S - WIDTH))*H + h];
        o = cvt8(*(const float4*)s, *(const float4*)(s + 4));
    } else if (use_inputs) {
        const float* s = &inputs[((long)b*S + (p - WIDTH))*H + h];
        o = cvt8(*(const float4*)s, *(const float4*)(s + 4));
    } else {
        o = *(const uint4*)&g_x[dir][((long)b*S + (p - WIDTH))*H + h];
    }
    *(uint4*)&g_pad[dir][((long)b*SP + p)*H + h] = o;
}

// ---------------- conv GEMM: y = relu(A_win @ W + b), fp16 mma ----------------
// M=16384, N=512, K=2560. CTA 128x256, warp 64x32 (16 warps), BK=32, 6-stage cp.async.
__global__ __launch_bounds__(512, 1)
void conv_gemm_kernel(const float* __restrict__ fwd_b, const float* __restrict__ bwd_b, int layer)
{
    extern __shared__ __align__(128) char dyn[];
    const uint32_t sb = smem_u32(dyn);

    const int dir = blockIdx.z;
    const float* bias = (dir ? bwd_b : fwd_b) + (long)layer * H;
    const __half* pad = g_pad[dir];
    const __half* cw  = g_cwT[dir * 3 + layer];
    const int off = dir ? WIDTH : 0;

    const int row0 = blockIdx.y * BM;
    const int bb = row0 / S, t0 = row0 % S;
    const int rowBase = bb * SP + t0 + off;
    const int n0 = blockIdx.x * BN;

    const int tid = threadIdx.x, warp = tid >> 5, lane = tid & 31;
    const int wm = warp >> 3, wn = warp & 7;       // 2 x 8
    const int g = lane >> 2, tig = lane & 3;
    const int lr = lane & 15, lc = lane >> 4;

    float d[4][4][4];
#pragma unroll
    for (int i = 0; i < 4; i++)
#pragma unroll
        for (int j = 0; j < 4; j++)
#pragma unroll
            for (int k = 0; k < 4; k++) d[i][j][k] = 0.0f;

    // staging maps
    const int aRow = tid >> 2, aCC = tid & 3;      // A: 128 rows x 4 chunks

    auto issue = [&](int s) {
        const int k0 = s * BK;
        const int w  = k0 >> 9;
        const int h0 = k0 & (H - 1);
        const uint32_t Ab = sb + (s % NSTG) * ASTGB;
        const uint32_t Bb = sb + NSTG * ASTGB + (s % NSTG) * BSTGB;
        const __half* Ag = pad + (size_t)(rowBase + aRow + w) * H + h0;
        cp16(Ab + aRow * AROWB + aCC * 16, Ag + aCC * 8);
        const __half* Bg = cw + (size_t)n0 * CIN + k0;
#pragma unroll
        for (int i = 0; i < 2; i++) {
            int ch = tid + i * 512;
            int rowb = ch >> 2, cc = ch & 3;
            cp16(Bb + rowb * AROWB + cc * 16, Bg + (size_t)rowb * CIN + cc * 8);
        }
    };

    issue(0); CP_COMMIT();
    issue(1); CP_COMMIT();
    issue(2); CP_COMMIT();
    issue(3); CP_COMMIT();
    issue(4); CP_COMMIT();

    const int NS = CIN / BK;   // 80
    const int kfirst = warp & 1;   // stagger: odd warps do ks=1 first
    for (int s = 0; s < NS; s++) {
        CP_WAIT4();
        __syncthreads();

        const uint32_t Ab = sb + (s % NSTG) * ASTGB;
        const uint32_t Bb = sb + NSTG * ASTGB + (s % NSTG) * BSTGB;
        const uint32_t aBase = Ab + (wm * 64 + lr) * AROWB + lc * 16;
        const uint32_t bBase = Bb + (wn * 32 + lr) * AROWB + lc * 16;
#pragma unroll
        for (int kk = 0; kk < 2; kk++) {
            const int ks = kfirst ^ kk;
            uint32_t a[4][4], bq[2][4];
#pragma unroll
            for (int mf = 0; mf < 4; mf++)
                LDSM_X4(a[mf][0], a[mf][1], a[mf][2], a[mf][3], aBase + mf * (16 * AROWB) + ks * 32);
#pragma unroll
            for (int ng = 0; ng < 2; ng++)
                LDSM_X4(bq[ng][0], bq[ng][1], bq[ng][2], bq[ng][3], bBase + ng * (16 * AROWB) + ks * 32);
            if (kk == 0) {   // defer cp.async burst past first fragment batch
                if (s + 5 < NS) issue(s + 5);
                CP_COMMIT();
            }
#pragma unroll
            for (int mf = 0; mf < 4; mf++)
#pragma unroll
                for (int nf = 0; nf < 4; nf++) {
                    int ng = nf >> 1, hi = nf & 1;
                    mma_f16(d[mf][nf], a[mf], bq[ng][hi], bq[ng][hi + 2]);
                }
        }
    }

    // epilogue: relu(acc + bias) -> g_x fp16
    __half* xo = g_x[dir];
#pragma unroll
    for (int mf = 0; mf < 4; mf++) {
        const size_t r = (size_t)row0 + wm * 64 + mf * 16 + g;
#pragma unroll
        for (int nf = 0; nf < 4; nf++) {
            const int c = n0 + wn * 32 + nf * 8 + 2 * tig;
            const float b0 = bias[c], b1 = bias[c + 1];
            __half2 v0 = __floats2half2_rn(fmaxf(d[mf][nf][0] + b0, 0.f), fmaxf(d[mf][nf][1] + b1, 0.f));
            __half2 v1 = __floats2half2_rn(fmaxf(d[mf][nf][2] + b0, 0.f), fmaxf(d[mf][nf][3] + b1, 0.f));
            *(__half2*)&xo[r * H + c]       = v0;
            *(__half2*)&xo[(r + 8) * H + c] = v1;
        }
    }
}

// ---------------- highway GEMM: fused sigmoid-gate epilogue, fp16 mma ----------------
// B interleaved: col 2j = nonlin_j, 2j+1 = gate_j. CTA 128 x 256 (=128 outputs). K=512.
__global__ __launch_bounds__(512, 1)
void hw_kernel(const float* __restrict__ fwd_hw_b, const float* __restrict__ bwd_hw_b,
               int layer, int step, float* __restrict__ out)
{
    extern __shared__ __align__(128) char dyn[];
    const uint32_t sb = smem_u32(dyn);

    const int dir = blockIdx.z;
    const float* hb   = (dir ? bwd_hw_b : fwd_hw_b) + ((long)layer * 2 + step) * 2 * H;
    const __half* hwt = g_hwT[(dir * 3 + layer) * 2 + step];
    const __half* src = step ? g_x2[dir] : g_x[dir];
    __half*       dst = step ? g_x [dir] : g_x2[dir];

    const int row0 = blockIdx.y * BM;
    const int n0   = blockIdx.x * BN;    // interleaved proj columns

    const int tid = threadIdx.x, warp = tid >> 5, lane = tid & 31;
    const int wm = warp >> 3, wn = warp & 7;
    const int g = lane >> 2, tig = lane & 3;
    const int lr = lane & 15, lc = lane >> 4;

    float d[4][4][4];
#pragma unroll
    for (int i = 0; i < 4; i++)
#pragma unroll
        for (int j = 0; j < 4; j++)
#pragma unroll
            for (int k = 0; k < 4; k++) d[i][j][k] = 0.0f;

    const int aRow = tid >> 2, aCC = tid & 3;

    auto issue = [&](int s) {
        const int k0 = s * BK;
        const uint32_t Ab = sb + (s % NSTG) * ASTGB;
        const uint32_t Bb = sb + NSTG * ASTGB + (s % NSTG) * BSTGB;
        const __half* Ag = src + (size_t)(row0 + aRow) * H + k0;
        cp16(Ab + aRow * AROWB + aCC * 16, Ag + aCC * 8);
        const __half* Bg = hwt + (size_t)n0 * H + k0;
#pragma unroll
        for (int i = 0; i < 2; i++) {
            int ch = tid + i * 512;
            int rowb = ch >> 2, cc = ch & 3;
            cp16(Bb + rowb * AROWB + cc * 16, Bg + (size_t)rowb * H + cc * 8);
        }
    };

    issue(0); CP_COMMIT();
    issue(1); CP_COMMIT();
    issue(2); CP_COMMIT();
    issue(3); CP_COMMIT();
    issue(4); CP_COMMIT();

    const int NS = H / BK;   // 16
    const int kfirst = warp & 1;
    for (int s = 0; s < NS; s++) {
        CP_WAIT4();
        __syncthreads();

        const uint32_t Ab = sb + (s % NSTG) * ASTGB;
        const uint32_t Bb = sb + NSTG * ASTGB + (s % NSTG) * BSTGB;
        const uint32_t aBase = Ab + (wm * 64 + lr) * AROWB + lc * 16;
        const uint32_t bBase = Bb + (wn * 32 + lr) * AROWB + lc * 16;
#pragma unroll
        for (int kk = 0; kk < 2; kk++) {
            const int ks = kfirst ^ kk;
            uint32_t a[4][4], bq[2][4];
#pragma unroll
            for (int mf = 0; mf < 4; mf++)
                LDSM_X4(a[mf][0], a[mf][1], a[mf][2], a[mf][3], aBase + mf * (16 * AROWB) + ks * 32);
#pragma unroll
            for (int ng = 0; ng < 2; ng++)
                LDSM_X4(bq[ng][0], bq[ng][1], bq[ng][2], bq[ng][3], bBase + ng * (16 * AROWB) + ks * 32);
            if (kk == 0) {
                if (s + 5 < NS) issue(s + 5);
                CP_COMMIT();
            }
#pragma unroll
            for (int mf = 0; mf < 4; mf++)
#pragma unroll
                for (int nf = 0; nf < 4; nf++) {
                    int ng = nf >> 1, hi = nf & 1;
                    mma_f16(d[mf][nf], a[mf], bq[ng][hi], bq[ng][hi + 2]);
                }
        }
    }

    // epilogue: c0/c1 = (nonlin, gate) of output j; rows g and g+8 via c2/c3.
#pragma unroll
    for (int mf = 0; mf < 4; mf++) {
        const size_t r0g = (size_t)row0 + wm * 64 + mf * 16 + g;
#pragma unroll
        for (int nf = 0; nf < 4; nf++) {
            const int j = (n0 + wn * 32 + nf * 8) / 2 + tig;
            const float bn = hb[j], bg = hb[H + j];
#pragma unroll
            for (int half_ = 0; half_ < 2; half_++) {
                const size_t r = r0g + half_ * 8;
                float nl = d[mf][nf][half_ * 2 + 0] + bn;
                float gt = d[mf][nf][half_ * 2 + 1] + bg;
                float xi = __half2float(src[r * H + j]);
                float gs = 1.0f / (1.0f + expf(-gt));
                float v  = gs * xi + (1.0f - gs) * fmaxf(nl, 0.0f);
                dst[r * H + j] = __float2half_rn(v);
                if (out) out[((size_t)layer * BSR + r) * (2*H) + (size_t)dir * H + j] = v;
            }
        }
    }
}

// ---------------- launch ----------------
extern "C" void kernel_launch(void* const* d_in, const int* in_sizes, int n_in,
                              void* d_out, int out_size)
{
    const float* inputs   = (const float*)d_in[0];
    const float* fwd_pads = (const float*)d_in[2];
    const float* bwd_pads = (const float*)d_in[3];
    const float* fwd_W    = (const float*)d_in[4];
    const float* fwd_b    = (const float*)d_in[5];
    const float* bwd_W    = (const float*)d_in[6];
    const float* bwd_b    = (const float*)d_in[7];
    const float* fwd_hw_W = (const float*)d_in[8];
    const float* fwd_hw_b = (const float*)d_in[9];
    const float* bwd_hw_W = (const float*)d_in[10];
    const float* bwd_hw_b = (const float*)d_in[11];
    float* out = (float*)d_out;

    cudaFuncSetAttribute(conv_gemm_kernel, cudaFuncAttributeMaxDynamicSharedMemorySize, DSMEM_BYTES);
    cudaFuncSetAttribute(hw_kernel,        cudaFuncAttributeMaxDynamicSharedMemorySize, DSMEM_BYTES);

    // one-time weight prep
    {
        dim3 bt(32, 8);
        dim3 gc(CIN / 32, H / 32, 6);
        prep_conv<<<gc, bt>>>(fwd_W, bwd_W);
        dim3 gh(H / 32, (2 * H) / 32, 12);
        prep_hw<<<gh, bt>>>(fwd_hw_W, bwd_hw_W);
    }

    const long n8 = (long)B * SP * H / 8;
    dim3 gp((unsigned)((n8 + 255) / 256), 2, 1);
    dim3 gcv(H / BN, BSR / BM, 2);        // 2 x 128 x 2
    dim3 ghw((2 * H) / BN, BSR / BM, 2);  // 4 x 128 x 2

    for (int layer = 0; layer < NL; layer++) {
        pad_kernel<<<gp, 256>>>(inputs, fwd_pads, bwd_pads, layer, layer == 0 ? 1 : 0);
        conv_gemm_kernel<<<gcv, 512, DSMEM_BYTES>>>(fwd_b, bwd_b, layer);
        hw_kernel<<<ghw, 512, DSMEM_BYTES>>>(fwd_hw_b, bwd_hw_b, layer, 0, nullptr);
        hw_kernel<<<ghw, 512, DSMEM_BYTES>>>(fwd_hw_b, bwd_hw_b, layer, 1, out);
    }
}

// round 15
// speedup vs baseline: 1.5212x; 1.5212x over previous
#include <cuda_runtime.h>
#include <cuda_fp16.h>
#include <cstdint>
#include <math.h>

#define NL 3
#define WIDTH 4
#define H 512
#define B 32
#define S 512
#define SP (S + 2*WIDTH)      // 520
#define CIN ((WIDTH+1)*H)     // 2560
#define BSR (B*S)             // 16384

// tiles: BM=128, BN=256, BK=32, 512 threads (16 warps, 2x8), warp tile 64x32
#define BM 128
#define BN 256
#define BK 32
#define NSTG 5
#define AROWB 80                      // smem row stride bytes (32 halfs + 16B pad)
#define ASTGB (BM * AROWB)            // 10240
#define BSTGB (BN * AROWB)            // 20480
#define DSMEM_BYTES (NSTG*(ASTGB + BSTGB))   // 153600

// ---------------- scratch (fp16 activations/weights) ----------------
__device__ __align__(256) __half g_pad[2][(size_t)B*SP*H];
__device__ __align__(256) __half g_x [2][(size_t)BSR*H];
__device__ __align__(256) __half g_x2[2][(size_t)BSR*H];
__device__ __align__(256) __half g_cwT[6][(size_t)H*CIN];      // conv W^T [n][k]
__device__ __align__(256) __half g_hwT[12][(size_t)(2*H)*H];   // hw W^T interleaved [n'][k]

// ---------------- helpers ----------------
__device__ __forceinline__ uint32_t smem_u32(const void* p) {
    uint32_t a;
    asm("{ .reg .u64 t; cvta.to.shared.u64 t, %1; cvt.u32.u64 %0, t; }" : "=r"(a) : "l"(p));
    return a;
}
__device__ __forceinline__ void cp16(uint32_t s, const void* g) {
    asm volatile("cp.async.ca.shared.global [%0], [%1], 16;" :: "r"(s), "l"(g));
}
#define CP_COMMIT() asm volatile("cp.async.commit_group;" ::: "memory")
#define CP_WAIT3()  asm volatile("cp.async.wait_group 3;" ::: "memory")

#define LDSM_X4(r0,r1,r2,r3,addr) \
    asm volatile("ldmatrix.sync.aligned.m8n8.x4.shared.b16 {%0,%1,%2,%3}, [%4];" \
        : "=r"(r0),"=r"(r1),"=r"(r2),"=r"(r3) : "r"(addr))

__device__ __forceinline__ void mma_f16(float* d, const uint32_t* a, uint32_t b0, uint32_t b1) {
    asm volatile("mma.sync.aligned.m16n8k16.row.col.f32.f16.f16.f32 "
        "{%0,%1,%2,%3},{%4,%5,%6,%7},{%8,%9},{%0,%1,%2,%3};"
        : "+f"(d[0]), "+f"(d[1]), "+f"(d[2]), "+f"(d[3])
        : "r"(a[0]), "r"(a[1]), "r"(a[2]), "r"(a[3]), "r"(b0), "r"(b1));
}

__device__ __forceinline__ uint4 cvt8(float4 a, float4 b) {
    __half2 h0 = __floats2half2_rn(a.x, a.y), h1 = __floats2half2_rn(a.z, a.w);
    __half2 h2 = __floats2half2_rn(b.x, b.y), h3 = __floats2half2_rn(b.z, b.w);
    uint4 r;
    r.x = *(uint32_t*)&h0; r.y = *(uint32_t*)&h1;
    r.z = *(uint32_t*)&h2; r.w = *(uint32_t*)&h3;
    return r;
}

// ---------------- prep: conv weight transpose [CIN][H] -> fp16 [H][CIN] ----------------
__global__ void prep_conv(const float* __restrict__ fwd_W, const float* __restrict__ bwd_W) {
    __shared__ float t[32][33];
    int z = blockIdx.z;               // dir*3 + layer
    int dir = z / 3, layer = z % 3;
    const float* src = (dir ? bwd_W : fwd_W) + (size_t)layer * CIN * H;
    __half* dst = g_cwT[z];
    int k0 = blockIdx.x * 32, n0 = blockIdx.y * 32;
    int tx = threadIdx.x, ty = threadIdx.y;
#pragma unroll
    for (int j = 0; j < 4; j++)
        t[ty + 8*j][tx] = src[(size_t)(k0 + ty + 8*j) * H + n0 + tx];
    __syncthreads();
#pragma unroll
    for (int j = 0; j < 4; j++)
        dst[(size_t)(n0 + ty + 8*j) * CIN + k0 + tx] = __float2half_rn(t[tx][ty + 8*j]);
}

// ---------------- prep: hw weight transpose + interleave -> fp16 [1024][512] ----------------
// dst row n' <- src col (n'&1)*512 + (n'>>1)   (even = nonlin, odd = gate)
__global__ void prep_hw(const float* __restrict__ fwd_hw_W, const float* __restrict__ bwd_hw_W) {
    __shared__ float t[32][33];
    int z = blockIdx.z;               // (dir*3+layer)*2 + step
    int dir = z / 6, rem = z % 6, layer = rem / 2, step = rem % 2;
    const float* src = (dir ? bwd_hw_W : fwd_hw_W) + ((size_t)layer * 2 + step) * (size_t)H * (2*H);
    __half* dst = g_hwT[z];
    int k0 = blockIdx.x * 32, np0 = blockIdx.y * 32;
    int j0 = np0 >> 1;
    int tx = threadIdx.x, ty = threadIdx.y;
    int half_ = tx >> 4, jj = tx & 15;
    int i = jj * 2 + half_;
#pragma unroll
    for (int j = 0; j < 4; j++)
        t[ty + 8*j][i] = src[(size_t)(k0 + ty + 8*j) * (2*H) + half_ * H + j0 + jj];
    __syncthreads();
#pragma unroll
    for (int j = 0; j < 4; j++)
        dst[(size_t)(np0 + ty + 8*j) * H + k0 + tx] = __float2half_rn(t[tx][ty + 8*j]);
}

// ---------------- pad kernel: build fp16 [B, S+8, H] padded sequence ----------------
__global__ void pad_kernel(const float* __restrict__ inputs,
                           const float* __restrict__ fwd_pads,
                           const float* __restrict__ bwd_pads,
                           int layer, int use_inputs)
{
    int dir = blockIdx.y;
    long idx = (long)blockIdx.x * blockDim.x + threadIdx.x;   // 8-half granularity
    const long n8 = (long)B * SP * H / 8;
    if (idx >= n8) return;
    long e = idx * 8;
    int h = (int)(e % H);
    long bp = e / H;
    int p = (int)(bp % SP);
    int b = (int)(bp / SP);

    uint4 o;
    if (p < WIDTH) {
        const float* s = &fwd_pads[((long)layer*WIDTH + p)*H + h];
        o = cvt8(*(const float4*)s, *(const float4*)(s + 4));
    } else if (p >= S + WIDTH) {
        const float* s = &bwd_pads[((long)layer*WIDTH + (p - S - WIDTH))*H + h];
        o = cvt8(*(const float4*)s, *(const float4*)(s + 4));
    } else if (use_inputs) {
        const float* s = &inputs[((long)b*S + (p - WIDTH))*H + h];
        o = cvt8(*(const float4*)s, *(const float4*)(s + 4));
    } else {
        o = *(const uint4*)&g_x[dir][((long)b*S + (p - WIDTH))*H + h];
    }
    *(uint4*)&g_pad[dir][((long)b*SP + p)*H + h] = o;
}

// ---------------- conv GEMM: y = relu(A_win @ W + b), fp16 mma ----------------
// M=16384, N=512, K=2560. CTA 128x256, warp 64x32 (16 warps), BK=32, 5-stage cp.async.
__global__ __launch_bounds__(512, 1)
void conv_gemm_kernel(const float* __restrict__ fwd_b, const float* __restrict__ bwd_b, int layer)
{
    extern __shared__ __align__(128) char dyn[];
    const uint32_t sb = smem_u32(dyn);

    const int dir = blockIdx.z;
    const float* bias = (dir ? bwd_b : fwd_b) + (long)layer * H;
    const __half* pad = g_pad[dir];
    const __half* cw  = g_cwT[dir * 3 + layer];
    const int off = dir ? WIDTH : 0;

    const int row0 = blockIdx.y * BM;
    const int bb = row0 / S, t0 = row0 % S;
    const int rowBase = bb * SP + t0 + off;
    const int n0 = blockIdx.x * BN;

    const int tid = threadIdx.x, warp = tid >> 5, lane = tid & 31;
    const int wm = warp >> 3, wn = warp & 7;       // 2 x 8
    const int g = lane >> 2, tig = lane & 3;
    const int lr = lane & 15, lc = lane >> 4;

    float d[4][4][4];
#pragma unroll
    for (int i = 0; i < 4; i++)
#pragma unroll
        for (int j = 0; j < 4; j++)
#pragma unroll
            for (int k = 0; k < 4; k++) d[i][j][k] = 0.0f;

    // staging maps
    const int aRow = tid >> 2, aCC = tid & 3;      // A: 128 rows x 4 chunks

    auto issue = [&](int s) {
        const int k0 = s * BK;
        const int w  = k0 >> 9;
        const int h0 = k0 & (H - 1);
        const uint32_t Ab = sb + (s % NSTG) * ASTGB;
        const uint32_t Bb = sb + NSTG * ASTGB + (s % NSTG) * BSTGB;
        const __half* Ag = pad + (size_t)(rowBase + aRow + w) * H + h0;
        cp16(Ab + aRow * AROWB + aCC * 16, Ag + aCC * 8);
        const __half* Bg = cw + (size_t)n0 * CIN + k0;
#pragma unroll
        for (int i = 0; i < 2; i++) {
            int ch = tid + i * 512;
            int rowb = ch >> 2, cc = ch & 3;
            cp16(Bb + rowb * AROWB + cc * 16, Bg + (size_t)rowb * CIN + cc * 8);
        }
    };

    issue(0); CP_COMMIT();
    issue(1); CP_COMMIT();
    issue(2); CP_COMMIT();
    issue(3); CP_COMMIT();

    const int NS = CIN / BK;   // 80
    for (int s = 0; s < NS; s++) {
        CP_WAIT3();
        __syncthreads();
        if (s + 4 < NS) issue(s + 4);
        CP_COMMIT();

        const uint32_t Ab = sb + (s % NSTG) * ASTGB;
        const uint32_t Bb = sb + NSTG * ASTGB + (s % NSTG) * BSTGB;
        const uint32_t aBase = Ab + (wm * 64 + lr) * AROWB + lc * 16;
        const uint32_t bBase = Bb + (wn * 32 + lr) * AROWB + lc * 16;
#pragma unroll
        for (int ks = 0; ks < 2; ks++) {
            uint32_t a[4][4], bq[2][4];
#pragma unroll
            for (int mf = 0; mf < 4; mf++)
                LDSM_X4(a[mf][0], a[mf][1], a[mf][2], a[mf][3], aBase + mf * (16 * AROWB) + ks * 32);
#pragma unroll
            for (int ng = 0; ng < 2; ng++)
                LDSM_X4(bq[ng][0], bq[ng][1], bq[ng][2], bq[ng][3], bBase + ng * (16 * AROWB) + ks * 32);
#pragma unroll
            for (int mf = 0; mf < 4; mf++)
#pragma unroll
                for (int nf = 0; nf < 4; nf++) {
                    int ng = nf >> 1, hi = nf & 1;
                    mma_f16(d[mf][nf], a[mf], bq[ng][hi], bq[ng][hi + 2]);
                }
        }
    }

    // epilogue: relu(acc + bias) -> g_x fp16
    __half* xo = g_x[dir];
#pragma unroll
    for (int mf = 0; mf < 4; mf++) {
        const size_t r = (size_t)row0 + wm * 64 + mf * 16 + g;
#pragma unroll
        for (int nf = 0; nf < 4; nf++) {
            const int c = n0 + wn * 32 + nf * 8 + 2 * tig;
            const float b0 = bias[c], b1 = bias[c + 1];
            __half2 v0 = __floats2half2_rn(fmaxf(d[mf][nf][0] + b0, 0.f), fmaxf(d[mf][nf][1] + b1, 0.f));
            __half2 v1 = __floats2half2_rn(fmaxf(d[mf][nf][2] + b0, 0.f), fmaxf(d[mf][nf][3] + b1, 0.f));
            *(__half2*)&xo[r * H + c]       = v0;
            *(__half2*)&xo[(r + 8) * H + c] = v1;
        }
    }
}

// ---------------- highway GEMM: fused sigmoid-gate epilogue, fp16 mma ----------------
// B interleaved: col 2j = nonlin_j, 2j+1 = gate_j. CTA 128 x 256 (=128 outputs). K=512.
__global__ __launch_bounds__(512, 1)
void hw_kernel(const float* __restrict__ fwd_hw_b, const float* __restrict__ bwd_hw_b,
               int layer, int step, float* __restrict__ out)
{
    extern __shared__ __align__(128) char dyn[];
    const uint32_t sb = smem_u32(dyn);

    const int dir = blockIdx.z;
    const float* hb   = (dir ? bwd_hw_b : fwd_hw_b) + ((long)layer * 2 + step) * 2 * H;
    const __half* hwt = g_hwT[(dir * 3 + layer) * 2 + step];
    const __half* src = step ? g_x2[dir] : g_x[dir];
    __half*       dst = step ? g_x [dir] : g_x2[dir];

    const int row0 = blockIdx.y * BM;
    const int n0   = blockIdx.x * BN;    // interleaved proj columns

    const int tid = threadIdx.x, warp = tid >> 5, lane = tid & 31;
    const int wm = warp >> 3, wn = warp & 7;
    const int g = lane >> 2, tig = lane & 3;
    const int lr = lane & 15, lc = lane >> 4;

    float d[4][4][4];
#pragma unroll
    for (int i = 0; i < 4; i++)
#pragma unroll
        for (int j = 0; j < 4; j++)
#pragma unroll
            for (int k = 0; k < 4; k++) d[i][j][k] = 0.0f;

    const int aRow = tid >> 2, aCC = tid & 3;

    auto issue = [&](int s) {
        const int k0 = s * BK;
        const uint32_t Ab = sb + (s % NSTG) * ASTGB;
        const uint32_t Bb = sb + NSTG * ASTGB + (s % NSTG) * BSTGB;
        const __half* Ag = src + (size_t)(row0 + aRow) * H + k0;
        cp16(Ab + aRow * AROWB + aCC * 16, Ag + aCC * 8);
        const __half* Bg = hwt + (size_t)n0 * H + k0;
#pragma unroll
        for (int i = 0; i < 2; i++) {
            int ch = tid + i * 512;
            int rowb = ch >> 2, cc = ch & 3;
            cp16(Bb + rowb * AROWB + cc * 16, Bg + (size_t)rowb * H + cc * 8);
        }
    };

    issue(0); CP_COMMIT();
    issue(1); CP_COMMIT();
    issue(2); CP_COMMIT();
    issue(3); CP_COMMIT();

    const int NS = H / BK;   // 16
    for (int s = 0; s < NS; s++) {
        CP_WAIT3();
        __syncthreads();
        if (s + 4 < NS) issue(s + 4);
        CP_COMMIT();

        const uint32_t Ab = sb + (s % NSTG) * ASTGB;
        const uint32_t Bb = sb + NSTG * ASTGB + (s % NSTG) * BSTGB;
        const uint32_t aBase = Ab + (wm * 64 + lr) * AROWB + lc * 16;
        const uint32_t bBase = Bb + (wn * 32 + lr) * AROWB + lc * 16;
#pragma unroll
        for (int ks = 0; ks < 2; ks++) {
            uint32_t a[4][4], bq[2][4];
#pragma unroll
            for (int mf = 0; mf < 4; mf++)
                LDSM_X4(a[mf][0], a[mf][1], a[mf][2], a[mf][3], aBase + mf * (16 * AROWB) + ks * 32);
#pragma unroll
            for (int ng = 0; ng < 2; ng++)
                LDSM_X4(bq[ng][0], bq[ng][1], bq[ng][2], bq[ng][3], bBase + ng * (16 * AROWB) + ks * 32);
#pragma unroll
            for (int mf = 0; mf < 4; mf++)
#pragma unroll
                for (int nf = 0; nf < 4; nf++) {
                    int ng = nf >> 1, hi = nf & 1;
                    mma_f16(d[mf][nf], a[mf], bq[ng][hi], bq[ng][hi + 2]);
                }
        }
    }

    // epilogue: c0/c1 = (nonlin, gate) of output j; rows g and g+8 via c2/c3.
#pragma unroll
    for (int mf = 0; mf < 4; mf++) {
        const size_t r0g = (size_t)row0 + wm * 64 + mf * 16 + g;
#pragma unroll
        for (int nf = 0; nf < 4; nf++) {
            const int j = (n0 + wn * 32 + nf * 8) / 2 + tig;
            const float bn = hb[j], bg = hb[H + j];
#pragma unroll
            for (int half_ = 0; half_ < 2; half_++) {
                const size_t r = r0g + half_ * 8;
                float nl = d[mf][nf][half_ * 2 + 0] + bn;
                float gt = d[mf][nf][half_ * 2 + 1] + bg;
                float xi = __half2float(src[r * H + j]);
                float gs = 1.0f / (1.0f + expf(-gt));
                float v  = gs * xi + (1.0f - gs) * fmaxf(nl, 0.0f);
                dst[r * H + j] = __float2half_rn(v);
                if (out) out[((size_t)layer * BSR + r) * (2*H) + (size_t)dir * H + j] = v;
            }
        }
    }
}

// ---------------- launch ----------------
extern "C" void kernel_launch(void* const* d_in, const int* in_sizes, int n_in,
                              void* d_out, int out_size)
{
    const float* inputs   = (const float*)d_in[0];
    const float* fwd_pads = (const float*)d_in[2];
    const float* bwd_pads = (const float*)d_in[3];
    const float* fwd_W    = (const float*)d_in[4];
    const float* fwd_b    = (const float*)d_in[5];
    const float* bwd_W    = (const float*)d_in[6];
    const float* bwd_b    = (const float*)d_in[7];
    const float* fwd_hw_W = (const float*)d_in[8];
    const float* fwd_hw_b = (const float*)d_in[9];
    const float* bwd_hw_W = (const float*)d_in[10];
    const float* bwd_hw_b = (const float*)d_in[11];
    float* out = (float*)d_out;

    cudaFuncSetAttribute(conv_gemm_kernel, cudaFuncAttributeMaxDynamicSharedMemorySize, DSMEM_BYTES);
    cudaFuncSetAttribute(hw_kernel,        cudaFuncAttributeMaxDynamicSharedMemorySize, DSMEM_BYTES);

    // one-time weight prep
    {
        dim3 bt(32, 8);
        dim3 gc(CIN / 32, H / 32, 6);
        prep_conv<<<gc, bt>>>(fwd_W, bwd_W);
        dim3 gh(H / 32, (2 * H) / 32, 12);
        prep_hw<<<gh, bt>>>(fwd_hw_W, bwd_hw_W);
    }

    const long n8 = (long)B * SP * H / 8;
    dim3 gp((unsigned)((n8 + 255) / 256), 2, 1);
    dim3 gcv(H / BN, BSR / BM, 2);        // 2 x 128 x 2
    dim3 ghw((2 * H) / BN, BSR / BM, 2);  // 4 x 128 x 2

    for (int layer = 0; layer < NL; layer++) {
        pad_kernel<<<gp, 256>>>(inputs, fwd_pads, bwd_pads, layer, layer == 0 ? 1 : 0);
        conv_gemm_kernel<<<gcv, 512, DSMEM_BYTES>>>(fwd_b, bwd_b, layer);
        hw_kernel<<<ghw, 512, DSMEM_BYTES>>>(fwd_hw_b, bwd_hw_b, layer, 0, nullptr);
        hw_kernel<<<ghw, 512, DSMEM_BYTES>>>(fwd_hw_b, bwd_hw_b, layer, 1, out);
    }
}

// round 16
// speedup vs baseline: 1.5583x; 1.0244x over previous
#include <cuda_runtime.h>
#include <cuda_fp16.h>
#include <cstdint>
#include <math.h>

#define NL 3
#define WIDTH 4
#define H 512
#define B 32
#define S 512
#define SP (S + 2*WIDTH)      // 520
#define CIN ((WIDTH+1)*H)     // 2560
#define BSR (B*S)             // 16384

// tiles: BM=128, BN=256, BK=32, 512 threads (16 warps, 2x8), warp tile 64x32
#define BM 128
#define BN 256
#define BK 32
#define NSTG 4
#define AROWB 80                      // smem row stride bytes (32 halfs + 16B pad)
#define ASTGB (BM * AROWB)            // 10240
#define BSTGB (BN * AROWB)            // 20480
#define DSMEM_BYTES (NSTG*(ASTGB + BSTGB))   // 122880

// ---------------- scratch (fp16 activations/weights) ----------------
__device__ __align__(256) __half g_pad[2][(size_t)B*SP*H];
__device__ __align__(256) __half g_x [2][(size_t)BSR*H];
__device__ __align__(256) __half g_x2[2][(size_t)BSR*H];
__device__ __align__(256) __half g_cwT[6][(size_t)H*CIN];      // conv W^T [n][k]
__device__ __align__(256) __half g_hwT[12][(size_t)(2*H)*H];   // hw W^T interleaved [n'][k]
__device__ __align__(256) __half g_fpads[NL][WIDTH][H];        // fp16 fwd pads
__device__ __align__(256) __half g_bpads[NL][WIDTH][H];        // fp16 bwd pads

// ---------------- helpers ----------------
__device__ __forceinline__ uint32_t smem_u32(const void* p) {
    uint32_t a;
    asm("{ .reg .u64 t; cvta.to.shared.u64 t, %1; cvt.u32.u64 %0, t; }" : "=r"(a) : "l"(p));
    return a;
}
__device__ __forceinline__ void cp16(uint32_t s, const void* g) {
    asm volatile("cp.async.ca.shared.global [%0], [%1], 16;" :: "r"(s), "l"(g));
}
#define CP_COMMIT() asm volatile("cp.async.commit_group;" ::: "memory")
#define CP_WAIT2()  asm volatile("cp.async.wait_group 2;" ::: "memory")

#define LDSM_X4(r0,r1,r2,r3,addr) \
    asm volatile("ldmatrix.sync.aligned.m8n8.x4.shared.b16 {%0,%1,%2,%3}, [%4];" \
        : "=r"(r0),"=r"(r1),"=r"(r2),"=r"(r3) : "r"(addr))

__device__ __forceinline__ void mma_f16(float* d, const uint32_t* a, uint32_t b0, uint32_t b1) {
    asm volatile("mma.sync.aligned.m16n8k16.row.col.f32.f16.f16.f32 "
        "{%0,%1,%2,%3},{%4,%5,%6,%7},{%8,%9},{%0,%1,%2,%3};"
        : "+f"(d[0]), "+f"(d[1]), "+f"(d[2]), "+f"(d[3])
        : "r"(a[0]), "r"(a[1]), "r"(a[2]), "r"(a[3]), "r"(b0), "r"(b1));
}

__device__ __forceinline__ uint4 cvt8(float4 a, float4 b) {
    __half2 h0 = __floats2half2_rn(a.x, a.y), h1 = __floats2half2_rn(a.z, a.w);
    __half2 h2 = __floats2half2_rn(b.x, b.y), h3 = __floats2half2_rn(b.z, b.w);
    uint4 r;
    r.x = *(uint32_t*)&h0; r.y = *(uint32_t*)&h1;
    r.z = *(uint32_t*)&h2; r.w = *(uint32_t*)&h3;
    return r;
}

// ---------------- prep: conv weight transpose [CIN][H] -> fp16 [H][CIN] ----------------
__global__ void prep_conv(const float* __restrict__ fwd_W, const float* __restrict__ bwd_W) {
    __shared__ float t[32][33];
    int z = blockIdx.z;               // dir*3 + layer
    int dir = z / 3, layer = z % 3;
    const float* src = (dir ? bwd_W : fwd_W) + (size_t)layer * CIN * H;
    __half* dst = g_cwT[z];
    int k0 = blockIdx.x * 32, n0 = blockIdx.y * 32;
    int tx = threadIdx.x, ty = threadIdx.y;
#pragma unroll
    for (int j = 0; j < 4; j++)
        t[ty + 8*j][tx] = src[(size_t)(k0 + ty + 8*j) * H + n0 + tx];
    __syncthreads();
#pragma unroll
    for (int j = 0; j < 4; j++)
        dst[(size_t)(n0 + ty + 8*j) * CIN + k0 + tx] = __float2half_rn(t[tx][ty + 8*j]);
}

// ---------------- prep: hw weight transpose + interleave -> fp16 [1024][512] ----------------
// dst row n' <- src col (n'&1)*512 + (n'>>1)   (even = nonlin, odd = gate)
__global__ void prep_hw(const float* __restrict__ fwd_hw_W, const float* __restrict__ bwd_hw_W) {
    __shared__ float t[32][33];
    int z = blockIdx.z;               // (dir*3+layer)*2 + step
    int dir = z / 6, rem = z % 6, layer = rem / 2, step = rem % 2;
    const float* src = (dir ? bwd_hw_W : fwd_hw_W) + ((size_t)layer * 2 + step) * (size_t)H * (2*H);
    __half* dst = g_hwT[z];
    int k0 = blockIdx.x * 32, np0 = blockIdx.y * 32;
    int j0 = np0 >> 1;
    int tx = threadIdx.x, ty = threadIdx.y;
    int half_ = tx >> 4, jj = tx & 15;
    int i = jj * 2 + half_;
#pragma unroll
    for (int j = 0; j < 4; j++)
        t[ty + 8*j][i] = src[(size_t)(k0 + ty + 8*j) * (2*H) + half_ * H + j0 + jj];
    __syncthreads();
#pragma unroll
    for (int j = 0; j < 4; j++)
        dst[(size_t)(np0 + ty + 8*j) * H + k0 + tx] = __float2half_rn(t[tx][ty + 8*j]);
}

// ---------------- prep: pads fp32 -> fp16 ----------------
__global__ void prep_pads(const float* __restrict__ fwd_pads, const float* __restrict__ bwd_pads) {
    int i = blockIdx.x * blockDim.x + threadIdx.x;
    if (i >= NL * WIDTH * H) return;
    ((__half*)g_fpads)[i] = __float2half_rn(fwd_pads[i]);
    ((__half*)g_bpads)[i] = __float2half_rn(bwd_pads[i]);
}

// ---------------- halo kernel: stamp 8 halo rows per batch per dir (layers >= 1) ----------------
__global__ void halo_kernel(int layer) {
    int idx = blockIdx.x * blockDim.x + threadIdx.x;  // uint4 (8-half) units
    const int total = 2 * B * 8 * (H / 8);            // 32768
    if (idx >= total) return;
    int h8   = idx & 63;          // 64 uint4 per row
    int rest = idx >> 6;
    int p   = rest & 7;
    int b   = (rest >> 3) & 31;
    int dir = rest >> 8;
    const __half* srcp = (p < WIDTH) ? &g_fpads[layer][p][0] : &g_bpads[layer][p - WIDTH][0];
    int pp = (p < WIDTH) ? p : (S + p);   // p in [4,8) -> S+4..S+7
    uint4 v = *(const uint4*)&srcp[h8 * 8];
    *(uint4*)&g_pad[dir][((size_t)b * SP + pp) * H + h8 * 8] = v;
}

// ---------------- pad kernel (layer 0 only): full fp16 padded sequence from inputs ----------------
__global__ void pad_kernel(const float* __restrict__ inputs,
                           const float* __restrict__ fwd_pads,
                           const float* __restrict__ bwd_pads)
{
    int dir = blockIdx.y;
    long idx = (long)blockIdx.x * blockDim.x + threadIdx.x;   // 8-half granularity
    const long n8 = (long)B * SP * H / 8;
    if (idx >= n8) return;
    long e = idx * 8;
    int h = (int)(e % H);
    long bp = e / H;
    int p = (int)(bp % SP);
    int b = (int)(bp / SP);

    uint4 o;
    if (p < WIDTH) {
        const float* s = &fwd_pads[(long)p * H + h];
        o = cvt8(*(const float4*)s, *(const float4*)(s + 4));
    } else if (p >= S + WIDTH) {
        const float* s = &bwd_pads[(long)(p - S - WIDTH) * H + h];
        o = cvt8(*(const float4*)s, *(const float4*)(s + 4));
    } else {
        const float* s = &inputs[((long)b*S + (p - WIDTH))*H + h];
        o = cvt8(*(const float4*)s, *(const float4*)(s + 4));
    }
    *(uint4*)&g_pad[dir][((long)b*SP + p)*H + h] = o;
}

// ---------------- conv GEMM: y = relu(A_win @ W + b), fp16 mma ----------------
// M=16384, N=512, K=2560. CTA 128x256, warp 64x32 (16 warps), BK=32, 4-stage cp.async.
__global__ __launch_bounds__(512, 1)
void conv_gemm_kernel(const float* __restrict__ fwd_b, const float* __restrict__ bwd_b, int layer)
{
    extern __shared__ __align__(128) char dyn[];
    const uint32_t sb = smem_u32(dyn);

    const int dir = blockIdx.z;
    const float* bias = (dir ? bwd_b : fwd_b) + (long)layer * H;
    const __half* pad = g_pad[dir];
    const __half* cw  = g_cwT[dir * 3 + layer];
    const int off = dir ? WIDTH : 0;

    const int row0 = blockIdx.y * BM;
    const int bb = row0 / S, t0 = row0 % S;
    const int rowBase = bb * SP + t0 + off;
    const int n0 = blockIdx.x * BN;

    const int tid = threadIdx.x, warp = tid >> 5, lane = tid & 31;
    const int wm = warp >> 3, wn = warp & 7;       // 2 x 8
    const int g = lane >> 2, tig = lane & 3;
    const int lr = lane & 15, lc = lane >> 4;

    float d[4][4][4];
#pragma unroll
    for (int i = 0; i < 4; i++)
#pragma unroll
        for (int j = 0; j < 4; j++)
#pragma unroll
            for (int k = 0; k < 4; k++) d[i][j][k] = 0.0f;

    // staging maps
    const int aRow = tid >> 2, aCC = tid & 3;      // A: 128 rows x 4 chunks

    auto issue = [&](int s) {
        const int k0 = s * BK;
        const int w  = k0 >> 9;
        const int h0 = k0 & (H - 1);
        const uint32_t Ab = sb + (s % NSTG) * ASTGB;
        const uint32_t Bb = sb + NSTG * ASTGB + (s % NSTG) * BSTGB;
        const __half* Ag = pad + (size_t)(rowBase + aRow + w) * H + h0;
        cp16(Ab + aRow * AROWB + aCC * 16, Ag + aCC * 8);
        const __half* Bg = cw + (size_t)n0 * CIN + k0;
#pragma unroll
        for (int i = 0; i < 2; i++) {
            int ch = tid + i * 512;
            int rowb = ch >> 2, cc = ch & 3;
            cp16(Bb + rowb * AROWB + cc * 16, Bg + (size_t)rowb * CIN + cc * 8);
        }
    };

    issue(0); CP_COMMIT();
    issue(1); CP_COMMIT();
    issue(2); CP_COMMIT();

    const int NS = CIN / BK;   // 80
    for (int s = 0; s < NS; s++) {
        CP_WAIT2();
        __syncthreads();
        if (s + 3 < NS) issue(s + 3);
        CP_COMMIT();

        const uint32_t Ab = sb + (s % NSTG) * ASTGB;
        const uint32_t Bb = sb + NSTG * ASTGB + (s % NSTG) * BSTGB;
        const uint32_t aBase = Ab + (wm * 64 + lr) * AROWB + lc * 16;
        const uint32_t bBase = Bb + (wn * 32 + lr) * AROWB + lc * 16;
#pragma unroll
        for (int ks = 0; ks < 2; ks++) {
            uint32_t a[4][4], bq[2][4];
#pragma unroll
            for (int mf = 0; mf < 4; mf++)
                LDSM_X4(a[mf][0], a[mf][1], a[mf][2], a[mf][3], aBase + mf * (16 * AROWB) + ks * 32);
#pragma unroll
            for (int ng = 0; ng < 2; ng++)
                LDSM_X4(bq[ng][0], bq[ng][1], bq[ng][2], bq[ng][3], bBase + ng * (16 * AROWB) + ks * 32);
#pragma unroll
            for (int mf = 0; mf < 4; mf++)
#pragma unroll
                for (int nf = 0; nf < 4; nf++) {
                    int ng = nf >> 1, hi = nf & 1;
                    mma_f16(d[mf][nf], a[mf], bq[ng][hi], bq[ng][hi + 2]);
                }
        }
    }

    // epilogue: relu(acc + bias) -> g_x fp16
    __half* xo = g_x[dir];
#pragma unroll
    for (int mf = 0; mf < 4; mf++) {
        const size_t r = (size_t)row0 + wm * 64 + mf * 16 + g;
#pragma unroll
        for (int nf = 0; nf < 4; nf++) {
            const int c = n0 + wn * 32 + nf * 8 + 2 * tig;
            const float b0 = bias[c], b1 = bias[c + 1];
            __half2 v0 = __floats2half2_rn(fmaxf(d[mf][nf][0] + b0, 0.f), fmaxf(d[mf][nf][1] + b1, 0.f));
            __half2 v1 = __floats2half2_rn(fmaxf(d[mf][nf][2] + b0, 0.f), fmaxf(d[mf][nf][3] + b1, 0.f));
            *(__half2*)&xo[r * H + c]       = v0;
            *(__half2*)&xo[(r + 8) * H + c] = v1;
        }
    }
}

// ---------------- highway GEMM: fused sigmoid-gate epilogue, fp16 mma ----------------
// B interleaved: col 2j = nonlin_j, 2j+1 = gate_j. CTA 128 x 256 (=128 outputs). K=512.
// step 0: g_x -> g_x2.  step 1: g_x2 -> g_pad interior (next layer's conv input) + out.
__global__ __launch_bounds__(512, 1)
void hw_kernel(const float* __restrict__ fwd_hw_b, const float* __restrict__ bwd_hw_b,
               int layer, int step, float* __restrict__ out)
{
    extern __shared__ __align__(128) char dyn[];
    const uint32_t sb = smem_u32(dyn);

    const int dir = blockIdx.z;
    const float* hb   = (dir ? bwd_hw_b : fwd_hw_b) + ((long)layer * 2 + step) * 2 * H;
    const __half* hwt = g_hwT[(dir * 3 + layer) * 2 + step];
    const __half* src = step ? g_x2[dir] : g_x[dir];
    __half*       dst = step ? g_pad[dir] : g_x2[dir];

    const int row0 = blockIdx.y * BM;
    const int n0   = blockIdx.x * BN;    // interleaved proj columns

    const int tid = threadIdx.x, warp = tid >> 5, lane = tid & 31;
    const int wm = warp >> 3, wn = warp & 7;
    const int g = lane >> 2, tig = lane & 3;
    const int lr = lane & 15, lc = lane >> 4;

    float d[4][4][4];
#pragma unroll
    for (int i = 0; i < 4; i++)
#pragma unroll
        for (int j = 0; j < 4; j++)
#pragma unroll
            for (int k = 0; k < 4; k++) d[i][j][k] = 0.0f;

    const int aRow = tid >> 2, aCC = tid & 3;

    auto issue = [&](int s) {
        const int k0 = s * BK;
        const uint32_t Ab = sb + (s % NSTG) * ASTGB;
        const uint32_t Bb = sb + NSTG * ASTGB + (s % NSTG) * BSTGB;
        const __half* Ag = src + (size_t)(row0 + aRow) * H + k0;
        cp16(Ab + aRow * AROWB + aCC * 16, Ag + aCC * 8);
        const __half* Bg = hwt + (size_t)n0 * H + k0;
#pragma unroll
        for (int i = 0; i < 2; i++) {
            int ch = tid + i * 512;
            int rowb = ch >> 2, cc = ch & 3;
            cp16(Bb + rowb * AROWB + cc * 16, Bg + (size_t)rowb * H + cc * 8);
        }
    };

    issue(0); CP_COMMIT();
    issue(1); CP_COMMIT();
    issue(2); CP_COMMIT();

    const int NS = H / BK;   // 16
    for (int s = 0; s < NS; s++) {
        CP_WAIT2();
        __syncthreads();
        if (s + 3 < NS) issue(s + 3);
        CP_COMMIT();

        const uint32_t Ab = sb + (s % NSTG) * ASTGB;
        const uint32_t Bb = sb + NSTG * ASTGB + (s % NSTG) * BSTGB;
        const uint32_t aBase = Ab + (wm * 64 + lr) * AROWB + lc * 16;
        const uint32_t bBase = Bb + (wn * 32 + lr) * AROWB + lc * 16;
#pragma unroll
        for (int ks = 0; ks < 2; ks++) {
            uint32_t a[4][4], bq[2][4];
#pragma unroll
            for (int mf = 0; mf < 4; mf++)
                LDSM_X4(a[mf][0], a[mf][1], a[mf][2], a[mf][3], aBase + mf * (16 * AROWB) + ks * 32);
#pragma unroll
            for (int ng = 0; ng < 2; ng++)
                LDSM_X4(bq[ng][0], bq[ng][1], bq[ng][2], bq[ng][3], bBase + ng * (16 * AROWB) + ks * 32);
#pragma unroll
            for (int mf = 0; mf < 4; mf++)
#pragma unroll
                for (int nf = 0; nf < 4; nf++) {
                    int ng = nf >> 1, hi = nf & 1;
                    mma_f16(d[mf][nf], a[mf], bq[ng][hi], bq[ng][hi + 2]);
                }
        }
    }

    // epilogue: c0/c1 = (nonlin, gate) of output j; rows g and g+8 via c2/c3.
#pragma unroll
    for (int mf = 0; mf < 4; mf++) {
        const size_t r0g = (size_t)row0 + wm * 64 + mf * 16 + g;
#pragma unroll
        for (int nf = 0; nf < 4; nf++) {
            const int j = (n0 + wn * 32 + nf * 8) / 2 + tig;
            const float bn = hb[j], bg = hb[H + j];
#pragma unroll
            for (int half_ = 0; half_ < 2; half_++) {
                const size_t r = r0g + half_ * 8;
                float nl = d[mf][nf][half_ * 2 + 0] + bn;
                float gt = d[mf][nf][half_ * 2 + 1] + bg;
                float xi = __half2float(src[r * H + j]);
                float gs = 1.0f / (1.0f + expf(-gt));
                float v  = gs * xi + (1.0f - gs) * fmaxf(nl, 0.0f);
                if (step) {
                    // write into padded layout: rp = b*SP + t + WIDTH, b = r>>9, t = r&511
                    const size_t rp = r + ((r >> 9) << 3) + WIDTH;
                    dst[rp * H + j] = __float2half_rn(v);
                    out[((size_t)layer * BSR + r) * (2*H) + (size_t)dir * H + j] = v;
                } else {
                    dst[r * H + j] = __float2half_rn(v);
                }
            }
        }
    }
}

// ---------------- launch ----------------
extern "C" void kernel_launch(void* const* d_in, const int* in_sizes, int n_in,
                              void* d_out, int out_size)
{
    const float* inputs   = (const float*)d_in[0];
    const float* fwd_pads = (const float*)d_in[2];
    const float* bwd_pads = (const float*)d_in[3];
    const float* fwd_W    = (const float*)d_in[4];
    const float* fwd_b    = (const float*)d_in[5];
    const float* bwd_W    = (const float*)d_in[6];
    const float* bwd_b    = (const float*)d_in[7];
    const float* fwd_hw_W = (const float*)d_in[8];
    const float* fwd_hw_b = (const float*)d_in[9];
    const float* bwd_hw_W = (const float*)d_in[10];
    const float* bwd_hw_b = (const float*)d_in[11];
    float* out = (float*)d_out;

    cudaFuncSetAttribute(conv_gemm_kernel, cudaFuncAttributeMaxDynamicSharedMemorySize, DSMEM_BYTES);
    cudaFuncSetAttribute(hw_kernel,        cudaFuncAttributeMaxDynamicSharedMemorySize, DSMEM_BYTES);

    // one-time weight/pad prep
    {
        dim3 bt(32, 8);
        dim3 gc(CIN / 32, H / 32, 6);
        prep_conv<<<gc, bt>>>(fwd_W, bwd_W);
        dim3 gh(H / 32, (2 * H) / 32, 12);
        prep_hw<<<gh, bt>>>(fwd_hw_W, bwd_hw_W);
        prep_pads<<<(NL * WIDTH * H + 255) / 256, 256>>>(fwd_pads, bwd_pads);
    }

    const long n8 = (long)B * SP * H / 8;
    dim3 gp((unsigned)((n8 + 255) / 256), 2, 1);
    dim3 gcv(H / BN, BSR / BM, 2);        // 2 x 128 x 2
    dim3 ghw((2 * H) / BN, BSR / BM, 2);  // 4 x 128 x 2

    for (int layer = 0; layer < NL; layer++) {
        if (layer == 0)
            pad_kernel<<<gp, 256>>>(inputs, fwd_pads, bwd_pads);
        else
            halo_kernel<<<128, 256>>>(layer);   // interior already written by prev hw step-1
        conv_gemm_kernel<<<gcv, 512, DSMEM_BYTES>>>(fwd_b, bwd_b, layer);
        hw_kernel<<<ghw, 512, DSMEM_BYTES>>>(fwd_hw_b, bwd_hw_b, layer, 0, out);
        hw_kernel<<<ghw, 512, DSMEM_BYTES>>>(fwd_hw_b, bwd_hw_b, layer, 1, out);
    }
}

// round 17
// speedup vs baseline: 1.5689x; 1.0068x over previous
#include <cuda_runtime.h>
#include <cuda_fp16.h>
#include <cstdint>
#include <math.h>

#define NL 3
#define WIDTH 4
#define H 512
#define B 32
#define S 512
#define SP (S + 2*WIDTH)      // 520
#define CIN ((WIDTH+1)*H)     // 2560
#define BSR (B*S)             // 16384

// tiles: BM=128, BN=256, BK=32, 512 threads (16 warps, 2x8), warp tile 64x32
#define BM 128
#define BN 256
#define BK 32
#define NSTG 4
#define AROWB 80                      // smem row stride bytes (32 halfs + 16B pad)
#define ASTGB (BM * AROWB)            // 10240
#define BSTGB (BN * AROWB)            // 20480
#define DSMEM_BYTES (NSTG*(ASTGB + BSTGB))   // 122880

// ---------------- scratch (fp16 activations/weights) ----------------
__device__ __align__(256) __half g_pad[2][(size_t)B*SP*H];
__device__ __align__(256) __half g_x [2][(size_t)BSR*H];
__device__ __align__(256) __half g_x2[2][(size_t)BSR*H];
__device__ __align__(256) __half g_cwT[6][(size_t)H*CIN];      // conv W^T [n][k]
__device__ __align__(256) __half g_hwT[12][(size_t)(2*H)*H];   // hw W^T interleaved [n'][k]
__device__ __align__(256) __half g_fpads[NL][WIDTH][H];        // fp16 fwd pads
__device__ __align__(256) __half g_bpads[NL][WIDTH][H];        // fp16 bwd pads

// ---------------- helpers ----------------
__device__ __forceinline__ uint32_t smem_u32(const void* p) {
    uint32_t a;
    asm("{ .reg .u64 t; cvta.to.shared.u64 t, %1; cvt.u32.u64 %0, t; }" : "=r"(a) : "l"(p));
    return a;
}
__device__ __forceinline__ void cp16(uint32_t s, const void* g) {
    asm volatile("cp.async.ca.shared.global [%0], [%1], 16;" :: "r"(s), "l"(g));
}
#define CP_COMMIT() asm volatile("cp.async.commit_group;" ::: "memory")
#define CP_WAIT2()  asm volatile("cp.async.wait_group 2;" ::: "memory")

#define LDSM_X4(r0,r1,r2,r3,addr) \
    asm volatile("ldmatrix.sync.aligned.m8n8.x4.shared.b16 {%0,%1,%2,%3}, [%4];" \
        : "=r"(r0),"=r"(r1),"=r"(r2),"=r"(r3) : "r"(addr))

__device__ __forceinline__ void mma_f16(float* d, const uint32_t* a, uint32_t b0, uint32_t b1) {
    asm volatile("mma.sync.aligned.m16n8k16.row.col.f32.f16.f16.f32 "
        "{%0,%1,%2,%3},{%4,%5,%6,%7},{%8,%9},{%0,%1,%2,%3};"
        : "+f"(d[0]), "+f"(d[1]), "+f"(d[2]), "+f"(d[3])
        : "r"(a[0]), "r"(a[1]), "r"(a[2]), "r"(a[3]), "r"(b0), "r"(b1));
}

__device__ __forceinline__ uint4 cvt8(float4 a, float4 b) {
    __half2 h0 = __floats2half2_rn(a.x, a.y), h1 = __floats2half2_rn(a.z, a.w);
    __half2 h2 = __floats2half2_rn(b.x, b.y), h3 = __floats2half2_rn(b.z, b.w);
    uint4 r;
    r.x = *(uint32_t*)&h0; r.y = *(uint32_t*)&h1;
    r.z = *(uint32_t*)&h2; r.w = *(uint32_t*)&h3;
    return r;
}

// ---------------- prep: conv weight transpose [CIN][H] -> fp16 [H][CIN] ----------------
__global__ void prep_conv(const float* __restrict__ fwd_W, const float* __restrict__ bwd_W) {
    __shared__ float t[32][33];
    int z = blockIdx.z;               // dir*3 + layer
    int dir = z / 3, layer = z % 3;
    const float* src = (dir ? bwd_W : fwd_W) + (size_t)layer * CIN * H;
    __half* dst = g_cwT[z];
    int k0 = blockIdx.x * 32, n0 = blockIdx.y * 32;
    int tx = threadIdx.x, ty = threadIdx.y;
#pragma unroll
    for (int j = 0; j < 4; j++)
        t[ty + 8*j][tx] = src[(size_t)(k0 + ty + 8*j) * H + n0 + tx];
    __syncthreads();
#pragma unroll
    for (int j = 0; j < 4; j++)
        dst[(size_t)(n0 + ty + 8*j) * CIN + k0 + tx] = __float2half_rn(t[tx][ty + 8*j]);
}

// ---------------- prep: hw weight transpose + interleave -> fp16 [1024][512] ----------------
// dst row n' <- src col (n'&1)*512 + (n'>>1)   (even = nonlin, odd = gate)
__global__ void prep_hw(const float* __restrict__ fwd_hw_W, const float* __restrict__ bwd_hw_W) {
    __shared__ float t[32][33];
    int z = blockIdx.z;               // (dir*3+layer)*2 + step
    int dir = z / 6, rem = z % 6, layer = rem / 2, step = rem % 2;
    const float* src = (dir ? bwd_hw_W : fwd_hw_W) + ((size_t)layer * 2 + step) * (size_t)H * (2*H);
    __half* dst = g_hwT[z];
    int k0 = blockIdx.x * 32, np0 = blockIdx.y * 32;
    int j0 = np0 >> 1;
    int tx = threadIdx.x, ty = threadIdx.y;
    int half_ = tx >> 4, jj = tx & 15;
    int i = jj * 2 + half_;
#pragma unroll
    for (int j = 0; j < 4; j++)
        t[ty + 8*j][i] = src[(size_t)(k0 + ty + 8*j) * (2*H) + half_ * H + j0 + jj];
    __syncthreads();
#pragma unroll
    for (int j = 0; j < 4; j++)
        dst[(size_t)(np0 + ty + 8*j) * H + k0 + tx] = __float2half_rn(t[tx][ty + 8*j]);
}

// ---------------- prep: pads fp32 -> fp16 ----------------
__global__ void prep_pads(const float* __restrict__ fwd_pads, const float* __restrict__ bwd_pads) {
    int i = blockIdx.x * blockDim.x + threadIdx.x;
    if (i >= NL * WIDTH * H) return;
    ((__half*)g_fpads)[i] = __float2half_rn(fwd_pads[i]);
    ((__half*)g_bpads)[i] = __float2half_rn(bwd_pads[i]);
}

// ---------------- halo kernel: stamp 8 halo rows per batch per dir (layers >= 1) ----------------
__global__ void halo_kernel(int layer) {
    int idx = blockIdx.x * blockDim.x + threadIdx.x;  // uint4 (8-half) units
    const int total = 2 * B * 8 * (H / 8);            // 32768
    if (idx >= total) return;
    int h8   = idx & 63;          // 64 uint4 per row
    int rest = idx >> 6;
    int p   = rest & 7;
    int b   = (rest >> 3) & 31;
    int dir = rest >> 8;
    const __half* srcp = (p < WIDTH) ? &g_fpads[layer][p][0] : &g_bpads[layer][p - WIDTH][0];
    int pp = (p < WIDTH) ? p : (S + p);   // p in [4,8) -> S+4..S+7
    uint4 v = *(const uint4*)&srcp[h8 * 8];
    *(uint4*)&g_pad[dir][((size_t)b * SP + pp) * H + h8 * 8] = v;
}

// ---------------- pad kernel (layer 0 only): single shared padded array (dirs identical) ----------------
__global__ void pad_kernel(const float* __restrict__ inputs,
                           const float* __restrict__ fwd_pads,
                           const float* __restrict__ bwd_pads)
{
    long idx = (long)blockIdx.x * blockDim.x + threadIdx.x;   // 8-half granularity
    const long n8 = (long)B * SP * H / 8;
    if (idx >= n8) return;
    long e = idx * 8;
    int h = (int)(e % H);
    long bp = e / H;
    int p = (int)(bp % SP);
    int b = (int)(bp / SP);

    uint4 o;
    if (p < WIDTH) {
        const float* s = &fwd_pads[(long)p * H + h];
        o = cvt8(*(const float4*)s, *(const float4*)(s + 4));
    } else if (p >= S + WIDTH) {
        const float* s = &bwd_pads[(long)(p - S - WIDTH) * H + h];
        o = cvt8(*(const float4*)s, *(const float4*)(s + 4));
    } else {
        const float* s = &inputs[((long)b*S + (p - WIDTH))*H + h];
        o = cvt8(*(const float4*)s, *(const float4*)(s + 4));
    }
    *(uint4*)&g_pad[0][((long)b*SP + p)*H + h] = o;
}

// ---------------- conv GEMM: y = relu(A_win @ W + b), fp16 mma ----------------
// M=16384, N=512, K=2560. CTA 128x256, warp 64x32 (16 warps), BK=32, 4-stage cp.async.
__global__ __launch_bounds__(512, 1)
void conv_gemm_kernel(const float* __restrict__ fwd_b, const float* __restrict__ bwd_b, int layer)
{
    extern __shared__ __align__(128) char dyn[];
    const uint32_t sb = smem_u32(dyn);

    const int dir = blockIdx.z;
    const float* bias = (dir ? bwd_b : fwd_b) + (long)layer * H;
    const __half* pad = g_pad[layer == 0 ? 0 : dir];   // layer 0: dirs share one padded array
    const __half* cw  = g_cwT[dir * 3 + layer];
    const int off = dir ? WIDTH : 0;

    const int row0 = blockIdx.y * BM;
    const int bb = row0 / S, t0 = row0 % S;
    const int rowBase = bb * SP + t0 + off;
    const int n0 = blockIdx.x * BN;

    const int tid = threadIdx.x, warp = tid >> 5, lane = tid & 31;
    const int wm = warp >> 3, wn = warp & 7;       // 2 x 8
    const int g = lane >> 2, tig = lane & 3;
    const int lr = lane & 15, lc = lane >> 4;

    float d[4][4][4];
#pragma unroll
    for (int i = 0; i < 4; i++)
#pragma unroll
        for (int j = 0; j < 4; j++)
#pragma unroll
            for (int k = 0; k < 4; k++) d[i][j][k] = 0.0f;

    // staging maps
    const int aRow = tid >> 2, aCC = tid & 3;      // A: 128 rows x 4 chunks

    auto issue = [&](int s) {
        const int k0 = s * BK;
        const int w  = k0 >> 9;
        const int h0 = k0 & (H - 1);
        const uint32_t Ab = sb + (s % NSTG) * ASTGB;
        const uint32_t Bb = sb + NSTG * ASTGB + (s % NSTG) * BSTGB;
        const __half* Ag = pad + (size_t)(rowBase + aRow + w) * H + h0;
        cp16(Ab + aRow * AROWB + aCC * 16, Ag + aCC * 8);
        const __half* Bg = cw + (size_t)n0 * CIN + k0;
#pragma unroll
        for (int i = 0; i < 2; i++) {
            int ch = tid + i * 512;
            int rowb = ch >> 2, cc = ch & 3;
            cp16(Bb + rowb * AROWB + cc * 16, Bg + (size_t)rowb * CIN + cc * 8);
        }
    };

    issue(0); CP_COMMIT();
    issue(1); CP_COMMIT();
    issue(2); CP_COMMIT();

    const int NS = CIN / BK;   // 80
    for (int s = 0; s < NS; s++) {
        CP_WAIT2();
        __syncthreads();
        if (s + 3 < NS) issue(s + 3);
        CP_COMMIT();

        const uint32_t Ab = sb + (s % NSTG) * ASTGB;
        const uint32_t Bb = sb + NSTG * ASTGB + (s % NSTG) * BSTGB;
        const uint32_t aBase = Ab + (wm * 64 + lr) * AROWB + lc * 16;
        const uint32_t bBase = Bb + (wn * 32 + lr) * AROWB + lc * 16;
#pragma unroll
        for (int ks = 0; ks < 2; ks++) {
            uint32_t a[4][4], bq[2][4];
#pragma unroll
            for (int mf = 0; mf < 4; mf++)
                LDSM_X4(a[mf][0], a[mf][1], a[mf][2], a[mf][3], aBase + mf * (16 * AROWB) + ks * 32);
#pragma unroll
            for (int ng = 0; ng < 2; ng++)
                LDSM_X4(bq[ng][0], bq[ng][1], bq[ng][2], bq[ng][3], bBase + ng * (16 * AROWB) + ks * 32);
#pragma unroll
            for (int mf = 0; mf < 4; mf++)
#pragma unroll
                for (int nf = 0; nf < 4; nf++) {
                    int ng = nf >> 1, hi = nf & 1;
                    mma_f16(d[mf][nf], a[mf], bq[ng][hi], bq[ng][hi + 2]);
                }
        }
    }

    // epilogue: relu(acc + bias) -> g_x fp16
    __half* xo = g_x[dir];
#pragma unroll
    for (int mf = 0; mf < 4; mf++) {
        const size_t r = (size_t)row0 + wm * 64 + mf * 16 + g;
#pragma unroll
        for (int nf = 0; nf < 4; nf++) {
            const int c = n0 + wn * 32 + nf * 8 + 2 * tig;
            const float b0 = bias[c], b1 = bias[c + 1];
            __half2 v0 = __floats2half2_rn(fmaxf(d[mf][nf][0] + b0, 0.f), fmaxf(d[mf][nf][1] + b1, 0.f));
            __half2 v1 = __floats2half2_rn(fmaxf(d[mf][nf][2] + b0, 0.f), fmaxf(d[mf][nf][3] + b1, 0.f));
            *(__half2*)&xo[r * H + c]       = v0;
            *(__half2*)&xo[(r + 8) * H + c] = v1;
        }
    }
}

// ---------------- highway GEMM: fused sigmoid-gate epilogue, fp16 mma ----------------
// B interleaved: col 2j = nonlin_j, 2j+1 = gate_j. CTA 128 x 256 (=128 outputs). K=512.
// step 0: g_x -> g_x2.  step 1: g_x2 -> g_pad interior (next layer's conv input) + out.
__global__ __launch_bounds__(512, 1)
void hw_kernel(const float* __restrict__ fwd_hw_b, const float* __restrict__ bwd_hw_b,
               int layer, int step, float* __restrict__ out)
{
    extern __shared__ __align__(128) char dyn[];
    const uint32_t sb = smem_u32(dyn);

    const int dir = blockIdx.z;
    const float* hb   = (dir ? bwd_hw_b : fwd_hw_b) + ((long)layer * 2 + step) * 2 * H;
    const __half* hwt = g_hwT[(dir * 3 + layer) * 2 + step];
    const __half* src = step ? g_x2[dir] : g_x[dir];
    __half*       dst = step ? g_pad[dir] : g_x2[dir];

    const int row0 = blockIdx.y * BM;
    const int n0   = blockIdx.x * BN;    // interleaved proj columns

    const int tid = threadIdx.x, warp = tid >> 5, lane = tid & 31;
    const int wm = warp >> 3, wn = warp & 7;
    const int g = lane >> 2, tig = lane & 3;
    const int lr = lane & 15, lc = lane >> 4;

    float d[4][4][4];
#pragma unroll
    for (int i = 0; i < 4; i++)
#pragma unroll
        for (int j = 0; j < 4; j++)
#pragma unroll
            for (int k = 0; k < 4; k++) d[i][j][k] = 0.0f;

    const int aRow = tid >> 2, aCC = tid & 3;

    auto issue = [&](int s) {
        const int k0 = s * BK;
        const uint32_t Ab = sb + (s % NSTG) * ASTGB;
        const uint32_t Bb = sb + NSTG * ASTGB + (s % NSTG) * BSTGB;
        const __half* Ag = src + (size_t)(row0 + aRow) * H + k0;
        cp16(Ab + aRow * AROWB + aCC * 16, Ag + aCC * 8);
        const __half* Bg = hwt + (size_t)n0 * H + k0;
#pragma unroll
        for (int i = 0; i < 2; i++) {
            int ch = tid + i * 512;
            int rowb = ch >> 2, cc = ch & 3;
            cp16(Bb + rowb * AROWB + cc * 16, Bg + (size_t)rowb * H + cc * 8);
        }
    };

    issue(0); CP_COMMIT();
    issue(1); CP_COMMIT();
    issue(2); CP_COMMIT();

    const int NS = H / BK;   // 16
    for (int s = 0; s < NS; s++) {
        CP_WAIT2();
        __syncthreads();
        if (s + 3 < NS) issue(s + 3);
        CP_COMMIT();

        const uint32_t Ab = sb + (s % NSTG) * ASTGB;
        const uint32_t Bb = sb + NSTG * ASTGB + (s % NSTG) * BSTGB;
        const uint32_t aBase = Ab + (wm * 64 + lr) * AROWB + lc * 16;
        const uint32_t bBase = Bb + (wn * 32 + lr) * AROWB + lc * 16;
#pragma unroll
        for (int ks = 0; ks < 2; ks++) {
            uint32_t a[4][4], bq[2][4];
#pragma unroll
            for (int mf = 0; mf < 4; mf++)
                LDSM_X4(a[mf][0], a[mf][1], a[mf][2], a[mf][3], aBase + mf * (16 * AROWB) + ks * 32);
#pragma unroll
            for (int ng = 0; ng < 2; ng++)
                LDSM_X4(bq[ng][0], bq[ng][1], bq[ng][2], bq[ng][3], bBase + ng * (16 * AROWB) + ks * 32);
#pragma unroll
            for (int mf = 0; mf < 4; mf++)
#pragma unroll
                for (int nf = 0; nf < 4; nf++) {
                    int ng = nf >> 1, hi = nf & 1;
                    mma_f16(d[mf][nf], a[mf], bq[ng][hi], bq[ng][hi + 2]);
                }
        }
    }

    // epilogue: c0/c1 = (nonlin, gate) of output j; rows g and g+8 via c2/c3.
#pragma unroll
    for (int mf = 0; mf < 4; mf++) {
        const size_t r0g = (size_t)row0 + wm * 64 + mf * 16 + g;
#pragma unroll
        for (int nf = 0; nf < 4; nf++) {
            const int j = (n0 + wn * 32 + nf * 8) / 2 + tig;
            const float bn = hb[j], bg = hb[H + j];
#pragma unroll
            for (int half_ = 0; half_ < 2; half_++) {
                const size_t r = r0g + half_ * 8;
                float nl = d[mf][nf][half_ * 2 + 0] + bn;
                float gt = d[mf][nf][half_ * 2 + 1] + bg;
                float xi = __half2float(src[r * H + j]);
                float gs = __fdividef(1.0f, 1.0f + __expf(-gt));
                float v  = gs * xi + (1.0f - gs) * fmaxf(nl, 0.0f);
                if (step) {
                    // write into padded layout: rp = b*SP + t + WIDTH, b = r>>9, t = r&511
                    const size_t rp = r + ((r >> 9) << 3) + WIDTH;
                    dst[rp * H + j] = __float2half_rn(v);
                    out[((size_t)layer * BSR + r) * (2*H) + (size_t)dir * H + j] = v;
                } else {
                    dst[r * H + j] = __float2half_rn(v);
                }
            }
        }
    }
}

// ---------------- launch ----------------
extern "C" void kernel_launch(void* const* d_in, const int* in_sizes, int n_in,
                              void* d_out, int out_size)
{
    const float* inputs   = (const float*)d_in[0];
    const float* fwd_pads = (const float*)d_in[2];
    const float* bwd_pads = (const float*)d_in[3];
    const float* fwd_W    = (const float*)d_in[4];
    const float* fwd_b    = (const float*)d_in[5];
    const float* bwd_W    = (const float*)d_in[6];
    const float* bwd_b    = (const float*)d_in[7];
    const float* fwd_hw_W = (const float*)d_in[8];
    const float* fwd_hw_b = (const float*)d_in[9];
    const float* bwd_hw_W = (const float*)d_in[10];
    const float* bwd_hw_b = (const float*)d_in[11];
    float* out = (float*)d_out;

    cudaFuncSetAttribute(conv_gemm_kernel, cudaFuncAttributeMaxDynamicSharedMemorySize, DSMEM_BYTES);
    cudaFuncSetAttribute(hw_kernel,        cudaFuncAttributeMaxDynamicSharedMemorySize, DSMEM_BYTES);

    // one-time weight/pad prep
    {
        dim3 bt(32, 8);
        dim3 gc(CIN / 32, H / 32, 6);
        prep_conv<<<gc, bt>>>(fwd_W, bwd_W);
        dim3 gh(H / 32, (2 * H) / 32, 12);
        prep_hw<<<gh, bt>>>(fwd_hw_W, bwd_hw_W);
        prep_pads<<<(NL * WIDTH * H + 255) / 256, 256>>>(fwd_pads, bwd_pads);
    }

    const long n8 = (long)B * SP * H / 8;
    dim3 gp((unsigned)((n8 + 255) / 256), 1, 1);
    dim3 gcv(H / BN, BSR / BM, 2);        // 2 x 128 x 2
    dim3 ghw((2 * H) / BN, BSR / BM, 2);  // 4 x 128 x 2

    for (int layer = 0; layer < NL; layer++) {
        if (layer == 0)
            pad_kernel<<<gp, 256>>>(inputs, fwd_pads, bwd_pads);
        else
            halo_kernel<<<128, 256>>>(layer);   // interior already written by prev hw step-1
        conv_gemm_kernel<<<gcv, 512, DSMEM_BYTES>>>(fwd_b, bwd_b, layer);
        hw_kernel<<<ghw, 512, DSMEM_BYTES>>>(fwd_hw_b, bwd_hw_b, layer, 0, out);
        hw_kernel<<<ghw, 512, DSMEM_BYTES>>>(fwd_hw_b, bwd_hw_b, layer, 1, out);
    }
}